// round 1
// baseline (speedup 1.0000x reference)
#include <cuda_runtime.h>
#include <cuda_bf16.h>

#define HID 256
#define TPB 128

// Per-thread registers hold the 2-D state y; weights live in SMEM and are read
// via broadcast LDS (all lanes read the same j). h is pre-folded into W2/b2 so
// each g-eval directly returns h*g(y).
__device__ __forceinline__ void geval(float y0, float y1,
                                      const float4* __restrict__ wA,
                                      const float*  __restrict__ wB,
                                      float hb20, float hb21,
                                      float& o0, float& o1)
{
    float a0 = 0.f, a1 = 0.f, a2 = 0.f, a3 = 0.f;
#pragma unroll 8
    for (int j = 0; j < HID; j += 2) {
        float4 w = wA[j];
        float pre = __fmaf_rn(w.x, y0, __fmaf_rn(w.y, y1, w.z));
        float t;
        asm("tanh.approx.f32 %0, %1;" : "=f"(t) : "f"(pre));
        a0 = __fmaf_rn(t, w.w,  a0);
        a1 = __fmaf_rn(t, wB[j], a1);

        float4 w2 = wA[j + 1];
        float pre2 = __fmaf_rn(w2.x, y0, __fmaf_rn(w2.y, y1, w2.z));
        float t2;
        asm("tanh.approx.f32 %0, %1;" : "=f"(t2) : "f"(pre2));
        a2 = __fmaf_rn(t2, w2.w,     a2);
        a3 = __fmaf_rn(t2, wB[j + 1], a3);
    }
    o0 = (a0 + a2) + hb20;
    o1 = (a1 + a3) + hb21;
}

__global__ __launch_bounds__(TPB)
void node_rk4_kernel(const float* __restrict__ x,
                     const float* __restrict__ W1,
                     const float* __restrict__ b1,
                     const float* __restrict__ W2,
                     const float* __restrict__ b2,
                     const float* __restrict__ Wf,
                     const float* __restrict__ bf,
                     const int*   __restrict__ tptr,
                     float* __restrict__ out,
                     int B)
{
    __shared__ float4 wA[HID];   // {W1[0][j], W1[1][j], b1[j], h*W2[j][0]}
    __shared__ float  wB[HID];   // h*W2[j][1]
    __shared__ float  sc[8];     // h*b2[0], h*b2[1], Wf00, Wf01, Wf10, Wf11, bf0, bf1
    __shared__ int    s_nsteps;

    const float h = 0.01f;
    const int tid = threadIdx.x;

    for (int j = tid; j < HID; j += TPB) {
        wA[j] = make_float4(W1[j], W1[HID + j], b1[j], h * W2[2 * j]);
        wB[j] = h * W2[2 * j + 1];
    }
    if (tid == 0) {
        sc[0] = h * b2[0]; sc[1] = h * b2[1];
        sc[2] = Wf[0]; sc[3] = Wf[1]; sc[4] = Wf[2]; sc[5] = Wf[3];
        sc[6] = bf[0]; sc[7] = bf[1];

        // Replicate Python's `while t <= tf: n += 1; t += h` with double accumulation.
        int tv = tptr[0];
        if (tv <= 0 || tv > 100000) {           // dtype fallback: scalar was float32
            tv = (int)__int_as_float(tv);
        }
        double tf = 0.1 * (double)tv;
        double tt = 0.0;
        int n = 0;
        while (tt <= tf) { n++; tt += 0.01; }
        s_nsteps = n;
    }
    __syncthreads();

    const int i = blockIdx.x * TPB + tid;
    if (i >= B) return;

    float y0 = x[2 * i + 0];
    float y1 = x[2 * i + 1];
    const int nsteps = s_nsteps;
    const float hb20 = sc[0], hb21 = sc[1];

    for (int s = 0; s < nsteps; s++) {
        float k10, k11, k20, k21, k30, k31, k40, k41;
        geval(y0, y1, wA, wB, hb20, hb21, k10, k11);
        geval(__fmaf_rn(0.5f, k10, y0), __fmaf_rn(0.5f, k11, y1),
              wA, wB, hb20, hb21, k20, k21);
        geval(__fmaf_rn(0.5f, k20, y0), __fmaf_rn(0.5f, k21, y1),
              wA, wB, hb20, hb21, k30, k31);
        geval(y0 + k30, y1 + k31, wA, wB, hb20, hb21, k40, k41);

        y0 += (k10 + 2.0f * (k20 + k30) + k40) * (1.0f / 6.0f);
        y1 += (k11 + 2.0f * (k21 + k31) + k41) * (1.0f / 6.0f);
    }

    // logits = y @ Wf + bf   (Wf row-major [2,2])
    float l0 = __fmaf_rn(y0, sc[2], __fmaf_rn(y1, sc[4], sc[6]));
    float l1 = __fmaf_rn(y0, sc[3], __fmaf_rn(y1, sc[5], sc[7]));

    float m  = fmaxf(l0, l1);
    float e0 = __expf(l0 - m);
    float e1 = __expf(l1 - m);
    float inv = 1.0f / (e0 + e1);

    out[2 * i + 0] = l0;
    out[2 * i + 1] = l1;
    out[2 * B + 2 * i + 0] = e0 * inv;
    out[2 * B + 2 * i + 1] = e1 * inv;
}

extern "C" void kernel_launch(void* const* d_in, const int* in_sizes, int n_in,
                              void* d_out, int out_size)
{
    const float* x  = (const float*)d_in[0];
    const float* W1 = (const float*)d_in[1];
    const float* b1 = (const float*)d_in[2];
    const float* W2 = (const float*)d_in[3];
    const float* b2 = (const float*)d_in[4];
    const float* Wf = (const float*)d_in[5];
    const float* bf = (const float*)d_in[6];
    const int*   t  = (const int*)d_in[7];
    float* out = (float*)d_out;

    const int B = in_sizes[0] / 2;
    const int grid = (B + TPB - 1) / TPB;
    node_rk4_kernel<<<grid, TPB>>>(x, W1, b1, W2, b2, Wf, bf, t, out, B);
}